// round 5
// baseline (speedup 1.0000x reference)
#include <cuda_runtime.h>

#define D 4096
#define H 64
#define S 64
#define EPSF 1e-5f

// Scratch (no allocations allowed)
__device__ float g_mix[4 * D];   // mix_r, mix_k, mix_v, mix_g
__device__ float g_rkvg[4 * D];  // r, k, v, g_lin
__device__ float g_y[D];         // gated, normalized wkv

// ---------------------------------------------------------------------------
// Kernel 1: LayerNorm(x) -> xx (= state1_out), then 4 token-mix vectors.
// 1 block, 256 threads, 16 elems/thread.
// ---------------------------------------------------------------------------
__global__ void ln_mix_kernel(const float* __restrict__ x,
                              const float* __restrict__ state1,
                              const float* __restrict__ tmk,
                              const float* __restrict__ tmv,
                              const float* __restrict__ tmr,
                              const float* __restrict__ tmg,
                              const float* __restrict__ ln1_w,
                              const float* __restrict__ ln1_b,
                              float* __restrict__ state1_out) {
    const int tid = threadIdx.x;  // 0..255
    float vals[16];
    float s = 0.f, sq = 0.f;
#pragma unroll
    for (int i = 0; i < 16; i++) {
        float v = x[tid + i * 256];
        vals[i] = v;
        s += v;
        sq += v * v;
    }
#pragma unroll
    for (int o = 16; o; o >>= 1) {
        s += __shfl_xor_sync(0xFFFFFFFFu, s, o);
        sq += __shfl_xor_sync(0xFFFFFFFFu, sq, o);
    }
    __shared__ float rs[8], rq[8];
    const int w = tid >> 5, l = tid & 31;
    if (l == 0) { rs[w] = s; rq[w] = sq; }
    __syncthreads();
    if (w == 0) {
        s = (l < 8) ? rs[l] : 0.f;
        sq = (l < 8) ? rq[l] : 0.f;
#pragma unroll
        for (int o = 4; o; o >>= 1) {
            s += __shfl_xor_sync(0xFFFFFFFFu, s, o);
            sq += __shfl_xor_sync(0xFFFFFFFFu, sq, o);
        }
        if (l == 0) { rs[0] = s; rq[0] = sq; }
    }
    __syncthreads();
    const float mean = rs[0] * (1.f / D);
    const float var = rq[0] * (1.f / D) - mean * mean;
    const float inv = rsqrtf(var + EPSF);
#pragma unroll
    for (int i = 0; i < 16; i++) {
        const int idx = tid + i * 256;
        const float xx = (vals[i] - mean) * inv * ln1_w[idx] + ln1_b[idx];
        state1_out[idx] = xx;
        const float s1 = state1[idx];
        const float d = xx - s1;
        g_mix[idx]         = s1 + d * tmr[idx];
        g_mix[D + idx]     = s1 + d * tmk[idx];
        g_mix[2 * D + idx] = s1 + d * tmv[idx];
        g_mix[3 * D + idx] = s1 + d * tmg[idx];
    }
}

// ---------------------------------------------------------------------------
// Kernel 2: fused 4-matrix GEMV. One warp per output row.
// Explicit MLP=4: each thread batch-loads 4 independent float4s (2KB/warp/iter)
// before consuming them. 16384 rows; grid = 2048 blocks x 256 threads.
// ---------------------------------------------------------------------------
__global__ void __launch_bounds__(256)
gemv4_kernel(const float* __restrict__ Wr,
             const float* __restrict__ Wk,
             const float* __restrict__ Wv,
             const float* __restrict__ Wg) {
    const int warp = threadIdx.x >> 5;
    const int lane = threadIdx.x & 31;
    const int row = blockIdx.x * 8 + warp;       // 0..16383
    const int mat = row >> 12;                   // 0..3
    const int r = row & (D - 1);

    const float* W = (mat == 0) ? Wr : (mat == 1) ? Wk : (mat == 2) ? Wv : Wg;
    const float4* __restrict__ W4 = (const float4*)(W + (size_t)r * D);
    const float4* __restrict__ x4 = (const float4*)(g_mix + mat * D);

    float a0 = 0.f, a1 = 0.f, a2 = 0.f, a3 = 0.f;
#pragma unroll 1
    for (int it = 0; it < 8; it++) {
        const int base = it * 128 + lane;        // float4 units; row = 1024 units
        float4 w0 = __ldg(W4 + base);
        float4 w1 = __ldg(W4 + base + 32);
        float4 w2 = __ldg(W4 + base + 64);
        float4 w3 = __ldg(W4 + base + 96);
        float4 v0 = x4[base];
        float4 v1 = x4[base + 32];
        float4 v2 = x4[base + 64];
        float4 v3 = x4[base + 96];
        a0 += w0.x * v0.x + w0.y * v0.y + w0.z * v0.z + w0.w * v0.w;
        a1 += w1.x * v1.x + w1.y * v1.y + w1.z * v1.z + w1.w * v1.w;
        a2 += w2.x * v2.x + w2.y * v2.y + w2.z * v2.z + w2.w * v2.w;
        a3 += w3.x * v3.x + w3.y * v3.y + w3.z * v3.z + w3.w * v3.w;
    }
    float acc = (a0 + a1) + (a2 + a3);
#pragma unroll
    for (int o = 16; o; o >>= 1) acc += __shfl_xor_sync(0xFFFFFFFFu, acc, o);
    if (lane == 0) g_rkvg[row] = acc;
}

// ---------------------------------------------------------------------------
// Kernel 3: per-head WKV + state2 update + InstanceNorm + SiLU gate.
// 64 blocks (one per head) x 256 threads: 4 i-slices of 16 rows each.
// ---------------------------------------------------------------------------
__global__ void wkv_kernel(const float* __restrict__ state2,
                           const float* __restrict__ time_decay,
                           const float* __restrict__ time_first,
                           const float* __restrict__ lnx_w,
                           const float* __restrict__ lnx_b,
                           float* __restrict__ state2_out) {
    const int h = blockIdx.x;
    const int tid = threadIdx.x;       // 0..255
    const int j = tid & 63;            // column 0..63
    const int i4 = tid >> 6;           // i-slice 0..3

    __shared__ float sr[S], sk[S], sv[S], std_[S];
    __shared__ float wpart[4 * S];
    __shared__ float pr[2], ss[2], qq[2];

    float gv = 0.f;
    if (tid < 64) {
        const float r = g_rkvg[h * S + j];
        const float k = g_rkvg[D + h * S + j];
        const float v = g_rkvg[2 * D + h * S + j];
        gv = g_rkvg[3 * D + h * S + j];
        const float tf = time_first[h * S + j];
        sr[j] = r;
        sk[j] = k;
        sv[j] = v;
        std_[j] = time_decay[h * S + j];
        float p = r * k * tf;
#pragma unroll
        for (int o = 16; o; o >>= 1) p += __shfl_xor_sync(0xFFFFFFFFu, p, o);
        if ((j & 31) == 0) pr[j >> 5] = p;
    }
    __syncthreads();

    const float* __restrict__ s2 = state2 + h * S * S;
    float* __restrict__ s2o = state2_out + h * S * S;

    const float vj = sv[j];
    float part = 0.f;
    const int i0 = i4 * 16;
#pragma unroll
    for (int ii = 0; ii < 16; ii++) {
        const int i = i0 + ii;
        const float s2v = s2[i * S + j];
        part += sr[i] * s2v;
        s2o[i * S + j] = sk[i] * vj + s2v * std_[i];
    }
    wpart[i4 * S + j] = part;
    __syncthreads();

    if (tid < 64) {
        const float sum_rktf = pr[0] + pr[1];
        float wkv = vj * sum_rktf + wpart[j] + wpart[S + j] +
                    wpart[2 * S + j] + wpart[3 * S + j];

        // InstanceNorm over the S columns of this head (2-warp reduce)
        float s = wkv, sq = wkv * wkv;
#pragma unroll
        for (int o = 16; o; o >>= 1) {
            s += __shfl_xor_sync(0xFFFFFFFFu, s, o);
            sq += __shfl_xor_sync(0xFFFFFFFFu, sq, o);
        }
        if ((j & 31) == 0) { ss[j >> 5] = s; qq[j >> 5] = sq; }
        __syncwarp();
        // cross-warp: make both partials visible
        __threadfence_block();
        // simple spin-free completion: both warps wrote before we read because
        // each warp only reads after writing its own slot; use bar among 64.
        asm volatile("bar.sync 1, 64;" ::: "memory");
        const float mu = (ss[0] + qq[0] * 0.f + ss[1]) * (1.f / S);
        const float var = (qq[0] + qq[1]) * (1.f / S) - mu * mu;
        const float inv = rsqrtf(var + EPSF);

        const float gate = gv / (1.f + __expf(-gv));  // SiLU
        g_y[h * S + j] =
            ((wkv - mu) * inv * lnx_w[h * S + j] + lnx_b[h * S + j]) * gate;
    }
}

// ---------------------------------------------------------------------------
// Kernel 4: out = x + Wo @ y. Warp-per-row GEMV with explicit MLP=4.
// 512 blocks x 256 threads.
// ---------------------------------------------------------------------------
__global__ void __launch_bounds__(256)
out_gemv_kernel(const float* __restrict__ Wo,
                const float* __restrict__ x,
                float* __restrict__ out) {
    const int warp = threadIdx.x >> 5;
    const int lane = threadIdx.x & 31;
    const int row = blockIdx.x * 8 + warp;  // 0..4095

    const float4* __restrict__ W4 = (const float4*)(Wo + (size_t)row * D);
    const float4* __restrict__ y4 = (const float4*)g_y;

    float a0 = 0.f, a1 = 0.f, a2 = 0.f, a3 = 0.f;
#pragma unroll 1
    for (int it = 0; it < 8; it++) {
        const int base = it * 128 + lane;
        float4 w0 = __ldg(W4 + base);
        float4 w1 = __ldg(W4 + base + 32);
        float4 w2 = __ldg(W4 + base + 64);
        float4 w3 = __ldg(W4 + base + 96);
        float4 v0 = y4[base];
        float4 v1 = y4[base + 32];
        float4 v2 = y4[base + 64];
        float4 v3 = y4[base + 96];
        a0 += w0.x * v0.x + w0.y * v0.y + w0.z * v0.z + w0.w * v0.w;
        a1 += w1.x * v1.x + w1.y * v1.y + w1.z * v1.z + w1.w * v1.w;
        a2 += w2.x * v2.x + w2.y * v2.y + w2.z * v2.z + w2.w * v2.w;
        a3 += w3.x * v3.x + w3.y * v3.y + w3.z * v3.z + w3.w * v3.w;
    }
    float acc = (a0 + a1) + (a2 + a3);
#pragma unroll
    for (int o = 16; o; o >>= 1) acc += __shfl_xor_sync(0xFFFFFFFFu, acc, o);
    if (lane == 0) out[row] = x[row] + acc;
}

// ---------------------------------------------------------------------------
// Launch. Output layout: [out(4096) | state1_out(4096) | state2_out(262144)]
// ---------------------------------------------------------------------------
extern "C" void kernel_launch(void* const* d_in, const int* in_sizes, int n_in,
                              void* d_out, int out_size) {
    (void)in_sizes; (void)n_in; (void)out_size;
    const float* x      = (const float*)d_in[0];
    const float* state1 = (const float*)d_in[1];
    const float* state2 = (const float*)d_in[2];
    const float* tmk    = (const float*)d_in[3];
    const float* tmv    = (const float*)d_in[4];
    const float* tmr    = (const float*)d_in[5];
    const float* tmg    = (const float*)d_in[6];
    const float* tdec   = (const float*)d_in[7];
    const float* tfirst = (const float*)d_in[8];
    const float* Wr     = (const float*)d_in[9];
    const float* Wk     = (const float*)d_in[10];
    const float* Wv     = (const float*)d_in[11];
    const float* Wg     = (const float*)d_in[12];
    const float* Wo     = (const float*)d_in[13];
    const float* ln1_w  = (const float*)d_in[14];
    const float* ln1_b  = (const float*)d_in[15];
    const float* lnx_w  = (const float*)d_in[16];
    const float* lnx_b  = (const float*)d_in[17];

    float* out        = (float*)d_out;
    float* state1_out = out + D;
    float* state2_out = out + 2 * D;

    ln_mix_kernel<<<1, 256>>>(x, state1, tmk, tmv, tmr, tmg, ln1_w, ln1_b,
                              state1_out);
    gemv4_kernel<<<2048, 256>>>(Wr, Wk, Wv, Wg);
    wkv_kernel<<<64, 256>>>(state2, tdec, tfirst, lnx_w, lnx_b, state2_out);
    out_gemv_kernel<<<512, 256>>>(Wo, x, out);
}